// round 5
// baseline (speedup 1.0000x reference)
#include <cuda_runtime.h>

// FeaturesLinear: out[b, :] = sum_{t<50} user_W[fid[b*50+t]] * rating_W[ridx[b*50+t]]
//                              + item_W[item_ids[b]] + bias
// Inputs (metadata order):
//   d_in[0] feature_ids int32 [819200]
//   d_in[1] ratings     f32   [819200]
//   d_in[2] segment_ids int32 [819200]   (contiguous: repeat(arange(B), 50) -> unused)
//   d_in[3] item_ids    int32 [16384]
//   d_in[4] user_W      f32   [100001, 128]
//   d_in[5] rating_W    f32   [10, 128]
//   d_in[6] item_W      f32   [100000, 128]
//   d_in[7] bias        f32   [128]
// Output: f32 [16384, 128]

#define BATCH  16384
#define HIST   50
#define DIM    128
#define WARPS_PER_CTA 8
#define THREADS (WARPS_PER_CTA * 32)

__global__ void __launch_bounds__(THREADS)
features_linear_kernel(const int*    __restrict__ feature_ids,
                       const float*  __restrict__ ratings,
                       const int*    __restrict__ item_ids,
                       const float4* __restrict__ user_W,    // [100001, 32] float4
                       const float4* __restrict__ rating_W,  // [10, 32] float4
                       const float4* __restrict__ item_W,    // [100000, 32] float4
                       const float4* __restrict__ bias,      // [32] float4
                       float4*       __restrict__ out)       // [16384, 32] float4
{
    // rating_W is 10*128 floats = 5 KB: cache in smem, read as float4.
    __shared__ float4 s_rw[10 * 32];

    const int tid = threadIdx.x;
    for (int i = tid; i < 10 * 32; i += THREADS)
        s_rw[i] = rating_W[i];
    __syncthreads();

    const int warp = tid >> 5;
    const int lane = tid & 31;
    const int row  = blockIdx.x * WARPS_PER_CTA + warp;   // one warp per output row
    if (row >= BATCH) return;

    const int base = row * HIST;

    float4 acc = make_float4(0.f, 0.f, 0.f, 0.f);

    // 50 history entries. Unroll to expose memory-level parallelism on the
    // 512B/warp user_W gathers (L2-latency ~250 cyc needs MLP + warp count).
    #pragma unroll 5
    for (int t = 0; t < HIST; t++) {
        const int   f = __ldg(&feature_ids[base + t]);           // warp-uniform broadcast
        const float r = __ldg(&ratings[base + t]);
        const int   ridx = __float2int_rn((r - 0.5f) * 2.0f);    // exact: r in {0.5,...,5.0}

        const float4 u  = __ldg(&user_W[f * 32 + lane]);         // the big gather
        const float4 rv = s_rw[ridx * 32 + lane];

        acc.x = fmaf(u.x, rv.x, acc.x);
        acc.y = fmaf(u.y, rv.y, acc.y);
        acc.z = fmaf(u.z, rv.z, acc.z);
        acc.w = fmaf(u.w, rv.w, acc.w);
    }

    const int iid = __ldg(&item_ids[row]);
    const float4 iv = __ldg(&item_W[iid * 32 + lane]);
    const float4 bv = __ldg(&bias[lane]);

    acc.x += iv.x + bv.x;
    acc.y += iv.y + bv.y;
    acc.z += iv.z + bv.z;
    acc.w += iv.w + bv.w;

    out[row * 32 + lane] = acc;
}

extern "C" void kernel_launch(void* const* d_in, const int* in_sizes, int n_in,
                              void* d_out, int out_size)
{
    const int*   feature_ids = (const int*)  d_in[0];
    const float* ratings     = (const float*)d_in[1];
    // d_in[2] segment_ids: structurally repeat(arange(BATCH), HIST) -> implicit
    const int*    item_ids = (const int*)   d_in[3];
    const float4* user_W   = (const float4*)d_in[4];
    const float4* rating_W = (const float4*)d_in[5];
    const float4* item_W   = (const float4*)d_in[6];
    const float4* bias     = (const float4*)d_in[7];
    float4*       out      = (float4*)      d_out;

    const int grid = BATCH / WARPS_PER_CTA;   // 2048 CTAs, 8 warps each
    features_linear_kernel<<<grid, THREADS>>>(
        feature_ids, ratings, item_ids, user_W, rating_W, item_W, bias, out);
}

// round 7
// speedup vs baseline: 1.0548x; 1.0548x over previous
#include <cuda_runtime.h>

// FeaturesLinear: out[b,:] = sum_{t<50} user_W[fid[b*50+t]] * rating_W[ridx[b*50+t]]
//                            + item_W[item_ids[b]] + bias
//
// Key algebraic restructure: only 10 distinct rating vectors exist, so
//   out[b] = sum_{r=0..9} rating_W[r] ⊙ ( sum_{t: ridx_t == r} user_W[fid_t] )
// Bucketing by r via warp ballots removes 50 LDS.128 per row (-> <=10) and the
// ids move from 100 broadcast LDGs per row into 4 coalesced lane loads + shuffles.
//
// Inputs (metadata order):
//   d_in[0] feature_ids int32 [819200]
//   d_in[1] ratings     f32   [819200]
//   d_in[2] segment_ids int32 [819200]  (contiguous repeat(arange(B),50) -> implicit)
//   d_in[3] item_ids    int32 [16384]
//   d_in[4] user_W      f32   [100001,128]
//   d_in[5] rating_W    f32   [10,128]
//   d_in[6] item_W      f32   [100000,128]
//   d_in[7] bias        f32   [128]
// Output: f32 [16384,128]

#define BATCH  16384
#define HIST   50
#define WARPS_PER_CTA 8
#define THREADS (WARPS_PER_CTA * 32)

__global__ void __launch_bounds__(THREADS)
features_linear_kernel(const int*    __restrict__ feature_ids,
                       const float*  __restrict__ ratings,
                       const int*    __restrict__ item_ids,
                       const float4* __restrict__ user_W,    // [100001, 32] float4
                       const float4* __restrict__ rating_W,  // [10, 32]     float4
                       const float4* __restrict__ item_W,    // [100000, 32] float4
                       const float4* __restrict__ bias,      // [32]         float4
                       float4*       __restrict__ out)       // [16384, 32]  float4
{
    __shared__ float4 s_rw[10 * 32];   // 5 KB rating table

    const int tid = threadIdx.x;
    for (int i = tid; i < 10 * 32; i += THREADS)
        s_rw[i] = rating_W[i];
    __syncthreads();

    const int warp = tid >> 5;
    const int lane = tid & 31;
    const int row  = blockIdx.x * WARPS_PER_CTA + warp;   // one warp per output row
    if (row >= BATCH) return;

    const int base = row * HIST;
    const unsigned FULL = 0xffffffffu;

    // --- Stage all 50 (fid, ridx) pairs into registers: 2 elements/lane ----
    // element A: t = lane (0..31); element B: t = 32+lane (valid for lane<18)
    const bool vB = (lane < (HIST - 32));
    const int   fidA = __ldg(&feature_ids[base + lane]);
    const float ratA = __ldg(&ratings[base + lane]);
    int   fidB = 0;
    float ratB = 0.f;
    if (vB) {
        fidB = __ldg(&feature_ids[base + 32 + lane]);
        ratB = __ldg(&ratings[base + 32 + lane]);
    }
    const int ridxA = __float2int_rn((ratA - 0.5f) * 2.0f);        // in [0,10)
    const int ridxB = vB ? __float2int_rn((ratB - 0.5f) * 2.0f) : -1;

    float4 acc = make_float4(0.f, 0.f, 0.f, 0.f);

    // --- Bucket loop: for each rating value, sum the raw user vectors ------
    #pragma unroll
    for (int r = 0; r < 10; ++r) {
        unsigned m1 = __ballot_sync(FULL, ridxA == r);   // warp-uniform masks
        unsigned m2 = __ballot_sync(FULL, ridxB == r);
        if ((m1 | m2) == 0u) continue;                   // uniform skip

        // Two independent accumulation chains for MLP=2 on the gathers.
        float4 a1 = make_float4(0.f, 0.f, 0.f, 0.f);
        float4 a2 = make_float4(0.f, 0.f, 0.f, 0.f);
        while (m1 | m2) {
            if (m1) {
                const int L = __ffs(m1) - 1;  m1 &= m1 - 1u;
                const int f = __shfl_sync(FULL, fidA, L);
                const float4 u = __ldg(&user_W[f * 32 + lane]);
                a1.x += u.x; a1.y += u.y; a1.z += u.z; a1.w += u.w;
            }
            if (m2) {
                const int L = __ffs(m2) - 1;  m2 &= m2 - 1u;
                const int f = __shfl_sync(FULL, fidB, L);
                const float4 u = __ldg(&user_W[f * 32 + lane]);
                a2.x += u.x; a2.y += u.y; a2.z += u.z; a2.w += u.w;
            }
        }

        const float4 rv = s_rw[r * 32 + lane];           // one LDS.128 per bucket
        acc.x = fmaf(a1.x + a2.x, rv.x, acc.x);
        acc.y = fmaf(a1.y + a2.y, rv.y, acc.y);
        acc.z = fmaf(a1.z + a2.z, rv.z, acc.z);
        acc.w = fmaf(a1.w + a2.w, rv.w, acc.w);
    }

    // --- Epilogue: item embedding + bias -----------------------------------
    const int iid = __ldg(&item_ids[row]);
    const float4 iv = __ldg(&item_W[iid * 32 + lane]);
    const float4 bv = __ldg(&bias[lane]);

    acc.x += iv.x + bv.x;
    acc.y += iv.y + bv.y;
    acc.z += iv.z + bv.z;
    acc.w += iv.w + bv.w;

    out[row * 32 + lane] = acc;
}

extern "C" void kernel_launch(void* const* d_in, const int* in_sizes, int n_in,
                              void* d_out, int out_size)
{
    const int*    feature_ids = (const int*)  d_in[0];
    const float*  ratings     = (const float*)d_in[1];
    // d_in[2] segment_ids: repeat(arange(BATCH), HIST) -> implicit in layout
    const int*    item_ids = (const int*)   d_in[3];
    const float4* user_W   = (const float4*)d_in[4];
    const float4* rating_W = (const float4*)d_in[5];
    const float4* item_W   = (const float4*)d_in[6];
    const float4* bias     = (const float4*)d_in[7];
    float4*       out      = (float4*)      d_out;

    const int grid = BATCH / WARPS_PER_CTA;   // 2048 CTAs, 8 warps each
    features_linear_kernel<<<grid, THREADS>>>(
        feature_ids, ratings, item_ids, user_W, rating_W, item_W, bias, out);
}